// round 1
// baseline (speedup 1.0000x reference)
#include <cuda_runtime.h>
#include <math.h>

#define BDIM   4
#define SDIM   2048
#define DDIM   4096
#define ODIM   4096
#define EDIM   8
#define RDIM   8
#define MDIM   (BDIM*SDIM)     // 8192
#define ERDIM  (EDIM*RDIM)     // 64
#define SCALING 2.0f           // lora_alpha / r = 16/8

// -------- scratch (no allocations allowed) --------
__device__ float g_h[MDIM * ERDIM];       // 2 MB: unweighted h = x @ lora_A^T
__device__ float g_xsum[BDIM * DDIM];     // column sums of x over S
__device__ float g_w[BDIM * EDIM];        // softmax(router) * SCALING

// ================= kernel 1: zero xsum =================
__global__ void zero_xsum_kernel() {
    int i = blockIdx.x * blockDim.x + threadIdx.x;
    if (i < BDIM * DDIM) g_xsum[i] = 0.0f;
}

// ================= kernel 2: xsum[b,d] = sum_s x[b,s,d] =================
// grid (16, 4, 4) = (d-chunk, s-segment, batch), 256 threads.
__global__ void xsum_kernel(const float* __restrict__ x) {
    int b  = blockIdx.z;
    int dc = blockIdx.x;
    int ss = blockIdx.y;
    int d  = dc * 256 + threadIdx.x;
    const float* p = x + ((size_t)(b * SDIM + ss * 512)) * DDIM + d;
    float acc = 0.0f;
#pragma unroll 8
    for (int s = 0; s < 512; ++s) acc += p[(size_t)s * DDIM];
    atomicAdd(&g_xsum[b * DDIM + d], acc);
}

// ================= kernel 3: router softmax =================
// 1 block, 1024 threads. warp w -> (b = w/8, e = w%8) dot product.
__global__ void router_kernel(const float* __restrict__ rW,
                              const float* __restrict__ rb) {
    __shared__ float logits[BDIM][EDIM];
    int w = threadIdx.x >> 5;
    int lane = threadIdx.x & 31;
    int b = w >> 3, e = w & 7;
    const float* xs = g_xsum + b * DDIM;
    const float* wr = rW + e * DDIM;
    float acc = 0.0f;
    for (int d = lane; d < DDIM; d += 32) acc += xs[d] * wr[d];
#pragma unroll
    for (int o = 16; o; o >>= 1) acc += __shfl_down_sync(0xffffffffu, acc, o);
    if (lane == 0) logits[b][e] = acc / (float)SDIM + rb[e];
    __syncthreads();
    if (threadIdx.x < BDIM) {
        int bb = threadIdx.x;
        float mx = -1e30f;
#pragma unroll
        for (int ee = 0; ee < EDIM; ++ee) mx = fmaxf(mx, logits[bb][ee]);
        float sum = 0.0f;
        float ex[EDIM];
#pragma unroll
        for (int ee = 0; ee < EDIM; ++ee) { ex[ee] = expf(logits[bb][ee] - mx); sum += ex[ee]; }
        float inv = SCALING / sum;
#pragma unroll
        for (int ee = 0; ee < EDIM; ++ee) g_w[bb * EDIM + ee] = ex[ee] * inv;
    }
}

// ================= kernel 4: h = x @ lora_A^T  (M=8192, N=64, K=4096) =====
// lora_A is [E,R,D] = flat [64,4096] row-major -> h[m,er] = sum_d x[m,d]*A2[er,d]
// Block tile 64x64, BK=16, 256 threads, 4x4 microtile.
__global__ __launch_bounds__(256) void h_kernel(const float* __restrict__ x,
                                                const float* __restrict__ lA) {
    __shared__ __align__(16) float Ax[16][68];
    __shared__ __align__(16) float Bw[16][68];
    int m0 = blockIdx.x * 64;
    int tid = threadIdx.x;
    int tx = tid & 15, ty = tid >> 4;
    int lr = tid >> 2;            // 0..63
    int lc = (tid & 3) << 2;      // 0,4,8,12
    const float4* xg = (const float4*)(x  + (size_t)(m0 + lr) * DDIM + lc);
    const float4* ag = (const float4*)(lA + (size_t)lr * DDIM + lc);
    float acc[4][4] = {};
    for (int k0 = 0; k0 < DDIM; k0 += 16) {
        float4 xa = xg[k0 >> 2];
        float4 ba = ag[k0 >> 2];
        __syncthreads();
        Ax[lc+0][lr]=xa.x; Ax[lc+1][lr]=xa.y; Ax[lc+2][lr]=xa.z; Ax[lc+3][lr]=xa.w;
        Bw[lc+0][lr]=ba.x; Bw[lc+1][lr]=ba.y; Bw[lc+2][lr]=ba.z; Bw[lc+3][lr]=ba.w;
        __syncthreads();
#pragma unroll
        for (int kk = 0; kk < 16; ++kk) {
            float4 a4 = *(const float4*)&Ax[kk][ty * 4];
            float4 b4 = *(const float4*)&Bw[kk][tx * 4];
            float a[4] = {a4.x, a4.y, a4.z, a4.w};
            float b[4] = {b4.x, b4.y, b4.z, b4.w};
#pragma unroll
            for (int i = 0; i < 4; ++i)
#pragma unroll
                for (int j = 0; j < 4; ++j) acc[i][j] += a[i] * b[j];
        }
    }
#pragma unroll
    for (int i = 0; i < 4; ++i) {
        float4 v = make_float4(acc[i][0], acc[i][1], acc[i][2], acc[i][3]);
        *(float4*)(g_h + (size_t)(m0 + ty * 4 + i) * ERDIM + tx * 4) = v;
    }
}

// ================= kernel 5: main fused GEMM + LoRA epilogue ==============
// out[m,n] = sum_k x[m,k]*W[n,k] + bias[n] + sum_er (w[b,e]*h[m,er])*B2[n,er]
// with B2[n, e*8+r] = lora_B[e, n, r]. Block 128x128, BK=8, double-buffered,
// 256 threads, 8x8 microtile. Epilogue reuses SMEM in 4 chunks of 16 er.
__global__ __launch_bounds__(256) void main_kernel(
        const float* __restrict__ x, const float* __restrict__ W,
        const float* __restrict__ bias, const float* __restrict__ lB,
        float* __restrict__ out) {
    __shared__ __align__(16) union SmemU {
        struct { float A[2][8][132]; float Bm[2][8][132]; } mn;   // 16896 B
        struct { float H[16][132];   float B2[16][132];   } ep;   // 16896 B
    } sm;
    int n0 = blockIdx.x * 128;
    int m0 = blockIdx.y * 128;
    int tid = threadIdx.x;
    int tx = tid & 15, ty = tid >> 4;
    int lr = tid >> 1;            // 0..127
    int lc = (tid & 1) << 2;      // 0 or 4
    const float4* xg = (const float4*)(x + (size_t)(m0 + lr) * DDIM + lc);
    const float4* wg = (const float4*)(W + (size_t)(n0 + lr) * DDIM + lc);
    float acc[8][8] = {};

    // prologue: tile 0 into buffer 0
    {
        float4 xa = xg[0], wa = wg[0];
        sm.mn.A [0][lc+0][lr]=xa.x; sm.mn.A [0][lc+1][lr]=xa.y;
        sm.mn.A [0][lc+2][lr]=xa.z; sm.mn.A [0][lc+3][lr]=xa.w;
        sm.mn.Bm[0][lc+0][lr]=wa.x; sm.mn.Bm[0][lc+1][lr]=wa.y;
        sm.mn.Bm[0][lc+2][lr]=wa.z; sm.mn.Bm[0][lc+3][lr]=wa.w;
    }
    __syncthreads();

    const int NT = DDIM / 8;   // 512
    for (int t = 0; t < NT; ++t) {
        int cur = t & 1, nxt = cur ^ 1;
        float4 xn, wn;
        if (t + 1 < NT) { xn = xg[(t + 1) * 2]; wn = wg[(t + 1) * 2]; }
#pragma unroll
        for (int kk = 0; kk < 8; ++kk) {
            float4 a0 = *(const float4*)&sm.mn.A [cur][kk][ty * 8];
            float4 a1 = *(const float4*)&sm.mn.A [cur][kk][ty * 8 + 4];
            float4 b0 = *(const float4*)&sm.mn.Bm[cur][kk][tx * 8];
            float4 b1 = *(const float4*)&sm.mn.Bm[cur][kk][tx * 8 + 4];
            float a[8] = {a0.x,a0.y,a0.z,a0.w,a1.x,a1.y,a1.z,a1.w};
            float b[8] = {b0.x,b0.y,b0.z,b0.w,b1.x,b1.y,b1.z,b1.w};
#pragma unroll
            for (int i = 0; i < 8; ++i)
#pragma unroll
                for (int j = 0; j < 8; ++j) acc[i][j] += a[i] * b[j];
        }
        if (t + 1 < NT) {
            sm.mn.A [nxt][lc+0][lr]=xn.x; sm.mn.A [nxt][lc+1][lr]=xn.y;
            sm.mn.A [nxt][lc+2][lr]=xn.z; sm.mn.A [nxt][lc+3][lr]=xn.w;
            sm.mn.Bm[nxt][lc+0][lr]=wn.x; sm.mn.Bm[nxt][lc+1][lr]=wn.y;
            sm.mn.Bm[nxt][lc+2][lr]=wn.z; sm.mn.Bm[nxt][lc+3][lr]=wn.w;
        }
        __syncthreads();
    }

    // ---------------- LoRA epilogue: acc += (w*h) @ B2^T ----------------
    int bidx = m0 / SDIM;          // all 128 rows share one batch
    // (last __syncthreads of main loop already ordered SMEM reuse)
    for (int ec = 0; ec < 4; ++ec) {
#pragma unroll
        for (int i = 0; i < 2; ++i) {
            int f   = i * 256 + tid;        // 0..511
            int row = f >> 2;               // 0..127
            int q   = f & 3;                // float4 index within 16 er
            int er  = ec * 16 + q * 4;      // er..er+3 share one expert e
            float wsc = g_w[bidx * EDIM + (er >> 3)];
            float4 hv = *(const float4*)(g_h + (size_t)(m0 + row) * ERDIM + er);
            sm.ep.H[q*4+0][row] = hv.x * wsc;
            sm.ep.H[q*4+1][row] = hv.y * wsc;
            sm.ep.H[q*4+2][row] = hv.z * wsc;
            sm.ep.H[q*4+3][row] = hv.w * wsc;
            int e2 = er >> 3, r0 = er & 7;
            float4 bv = *(const float4*)(lB + (size_t)e2 * ODIM * RDIM
                                            + (size_t)(n0 + row) * RDIM + r0);
            sm.ep.B2[q*4+0][row] = bv.x;
            sm.ep.B2[q*4+1][row] = bv.y;
            sm.ep.B2[q*4+2][row] = bv.z;
            sm.ep.B2[q*4+3][row] = bv.w;
        }
        __syncthreads();
#pragma unroll
        for (int kk = 0; kk < 16; ++kk) {
            float4 a0 = *(const float4*)&sm.ep.H [kk][ty * 8];
            float4 a1 = *(const float4*)&sm.ep.H [kk][ty * 8 + 4];
            float4 b0 = *(const float4*)&sm.ep.B2[kk][tx * 8];
            float4 b1 = *(const float4*)&sm.ep.B2[kk][tx * 8 + 4];
            float a[8] = {a0.x,a0.y,a0.z,a0.w,a1.x,a1.y,a1.z,a1.w};
            float b[8] = {b0.x,b0.y,b0.z,b0.w,b1.x,b1.y,b1.z,b1.w};
#pragma unroll
            for (int i = 0; i < 8; ++i)
#pragma unroll
                for (int j = 0; j < 8; ++j) acc[i][j] += a[i] * b[j];
        }
        __syncthreads();
    }

    // ---------------- store with bias ----------------
    float breg[8];
#pragma unroll
    for (int j = 0; j < 8; ++j) breg[j] = bias[n0 + tx * 8 + j];
#pragma unroll
    for (int i = 0; i < 8; ++i) {
        int gm = m0 + ty * 8 + i;
        float4 v0 = make_float4(acc[i][0]+breg[0], acc[i][1]+breg[1],
                                acc[i][2]+breg[2], acc[i][3]+breg[3]);
        float4 v1 = make_float4(acc[i][4]+breg[4], acc[i][5]+breg[5],
                                acc[i][6]+breg[6], acc[i][7]+breg[7]);
        *(float4*)(out + (size_t)gm * ODIM + n0 + tx * 8)     = v0;
        *(float4*)(out + (size_t)gm * ODIM + n0 + tx * 8 + 4) = v1;
    }
}

// ================= launcher =================
extern "C" void kernel_launch(void* const* d_in, const int* in_sizes, int n_in,
                              void* d_out, int out_size) {
    const float* x    = (const float*)d_in[0];   // [B,S,D]
    const float* Wb   = (const float*)d_in[1];   // [O,D]
    const float* bb   = (const float*)d_in[2];   // [O]
    const float* lA   = (const float*)d_in[3];   // [E,R,D]
    const float* lBm  = (const float*)d_in[4];   // [E,O,R]
    const float* rW   = (const float*)d_in[5];   // [E,D]
    const float* rb   = (const float*)d_in[6];   // [E]
    float* out = (float*)d_out;                  // [B,S,O]

    zero_xsum_kernel<<<16, 1024>>>();
    xsum_kernel<<<dim3(16, 4, 4), 256>>>(x);
    router_kernel<<<1, 1024>>>(rW, rb);
    h_kernel<<<MDIM / 64, 256>>>(x, lA);
    main_kernel<<<dim3(ODIM / 128, MDIM / 128), 256>>>(x, Wb, bb, lBm, out);
}

// round 3
// speedup vs baseline: 2.9097x; 2.9097x over previous
#include <cuda_runtime.h>
#include <cuda_bf16.h>
#include <stdint.h>
#include <math.h>

#define BDIM   4
#define SDIM   2048
#define DDIM   4096
#define ODIM   4096
#define EDIM   8
#define RDIM   8
#define MDIM   (BDIM*SDIM)     // 8192
#define ERDIM  64
#define SCALING 2.0f

// ---------------- scratch (static device globals; no allocations) -------
__device__ __nv_bfloat16 g_xhi[(size_t)MDIM * DDIM];   // 64 MB
__device__ __nv_bfloat16 g_xlo[(size_t)MDIM * DDIM];   // 64 MB
__device__ __nv_bfloat16 g_whi[(size_t)ODIM * DDIM];   // 32 MB
__device__ __nv_bfloat16 g_wlo[(size_t)ODIM * DDIM];   // 32 MB
__device__ float g_h[MDIM * ERDIM];                    // 2 MB
__device__ float g_xsum[BDIM * DDIM];
__device__ float g_w[BDIM * EDIM];

// ---------------- helpers ----------------
__device__ __forceinline__ uint32_t cvta_smem(const void* p) {
    return (uint32_t)__cvta_generic_to_shared(p);
}
__device__ __forceinline__ void cp16(uint32_t dst, const void* src) {
    asm volatile("cp.async.cg.shared.global [%0], [%1], 16;"
                 :: "r"(dst), "l"(src) : "memory");
}
__device__ __forceinline__ void cp_commit() {
    asm volatile("cp.async.commit_group;" ::: "memory");
}
__device__ __forceinline__ void cp_wait0() {
    asm volatile("cp.async.wait_group 0;" ::: "memory");
}
__device__ __forceinline__ void ldsm4(uint32_t a, uint32_t* r) {
    asm volatile("ldmatrix.sync.aligned.m8n8.x4.shared.b16 {%0,%1,%2,%3}, [%4];"
                 : "=r"(r[0]), "=r"(r[1]), "=r"(r[2]), "=r"(r[3]) : "r"(a));
}
__device__ __forceinline__ void mma_bf16(float* d, const uint32_t* a,
                                         uint32_t b0, uint32_t b1) {
    asm volatile(
        "mma.sync.aligned.m16n8k16.row.col.f32.bf16.bf16.f32 "
        "{%0,%1,%2,%3}, {%4,%5,%6,%7}, {%8,%9}, {%0,%1,%2,%3};"
        : "+f"(d[0]), "+f"(d[1]), "+f"(d[2]), "+f"(d[3])
        : "r"(a[0]), "r"(a[1]), "r"(a[2]), "r"(a[3]), "r"(b0), "r"(b1));
}

// split fp32x4 into bf16 hi/lo packed pairs
__device__ __forceinline__ void split4(float4 v, uint2& hi, uint2& lo) {
    __nv_bfloat16 hx = __float2bfloat16_rn(v.x), hy = __float2bfloat16_rn(v.y),
                  hz = __float2bfloat16_rn(v.z), hw = __float2bfloat16_rn(v.w);
    __nv_bfloat162 h01 = __halves2bfloat162(hx, hy);
    __nv_bfloat162 h23 = __halves2bfloat162(hz, hw);
    __nv_bfloat162 l01 = __floats2bfloat162_rn(v.x - __bfloat162float(hx),
                                               v.y - __bfloat162float(hy));
    __nv_bfloat162 l23 = __floats2bfloat162_rn(v.z - __bfloat162float(hz),
                                               v.w - __bfloat162float(hw));
    hi.x = *reinterpret_cast<uint32_t*>(&h01);
    hi.y = *reinterpret_cast<uint32_t*>(&h23);
    lo.x = *reinterpret_cast<uint32_t*>(&l01);
    lo.y = *reinterpret_cast<uint32_t*>(&l23);
}

// ================= kernel: zero scratch =================
__global__ void zero_kernel() {
    int i = blockIdx.x * 1024 + threadIdx.x;
    if (i < BDIM * DDIM) g_xsum[i] = 0.0f;
    if (i < MDIM * ERDIM) g_h[i] = 0.0f;
}

// ================= kernel: convert x -> bf16 hi/lo + column sums ========
__global__ void convx_kernel(const float* __restrict__ x) {
    int b = blockIdx.z;
    int d = blockIdx.x * 256 + threadIdx.x;
    int s0 = blockIdx.y * 128;
    size_t base = ((size_t)(b * SDIM + s0)) * DDIM + d;
    float acc = 0.0f;
#pragma unroll 4
    for (int s = 0; s < 128; ++s) {
        size_t idx = base + (size_t)s * DDIM;
        float v = x[idx];
        __nv_bfloat16 h = __float2bfloat16_rn(v);
        g_xhi[idx] = h;
        g_xlo[idx] = __float2bfloat16_rn(v - __bfloat162float(h));
        acc += v;
    }
    atomicAdd(&g_xsum[b * DDIM + d], acc);
}

// ================= kernel: convert W -> bf16 hi/lo =================
__global__ void convw_kernel(const float* __restrict__ W) {
    size_t j = (size_t)blockIdx.x * 256 + threadIdx.x;
    float4 v = ((const float4*)W)[j];
    uint2 hi, lo;
    split4(v, hi, lo);
    ((uint2*)g_whi)[j] = hi;
    ((uint2*)g_wlo)[j] = lo;
}

// ================= kernel: router softmax =================
__global__ void router_kernel(const float* __restrict__ rW,
                              const float* __restrict__ rb) {
    __shared__ float logits[BDIM][EDIM];
    int w = threadIdx.x >> 5;
    int lane = threadIdx.x & 31;
    int b = w >> 3, e = w & 7;
    const float* xs = g_xsum + b * DDIM;
    const float* wr = rW + e * DDIM;
    float acc = 0.0f;
    for (int d = lane; d < DDIM; d += 32) acc += xs[d] * wr[d];
#pragma unroll
    for (int o = 16; o; o >>= 1) acc += __shfl_down_sync(0xffffffffu, acc, o);
    if (lane == 0) logits[b][e] = acc / (float)SDIM + rb[e];
    __syncthreads();
    if (threadIdx.x < BDIM) {
        int bb = threadIdx.x;
        float mx = -1e30f;
#pragma unroll
        for (int ee = 0; ee < EDIM; ++ee) mx = fmaxf(mx, logits[bb][ee]);
        float sum = 0.0f;
        float ex[EDIM];
#pragma unroll
        for (int ee = 0; ee < EDIM; ++ee) { ex[ee] = expf(logits[bb][ee] - mx); sum += ex[ee]; }
        float inv = SCALING / sum;
#pragma unroll
        for (int ee = 0; ee < EDIM; ++ee) g_w[bb * EDIM + ee] = ex[ee] * inv;
    }
}

// ================= kernel: h = x @ lora_A^T (k-split x4, atomic) ========
__global__ __launch_bounds__(256) void h_kernel(const float* __restrict__ x,
                                                const float* __restrict__ lA) {
    __shared__ __align__(16) float Ax[16][68];
    __shared__ __align__(16) float Bw[16][68];
    int m0 = blockIdx.x * 64;
    int kbase = blockIdx.y * 1024;
    int tid = threadIdx.x;
    int tx = tid & 15, ty = tid >> 4;
    int lr = tid >> 2;
    int lc = (tid & 3) << 2;
    const float4* xg = (const float4*)(x  + (size_t)(m0 + lr) * DDIM + kbase + lc);
    const float4* ag = (const float4*)(lA + (size_t)lr * DDIM + kbase + lc);
    float acc[4][4] = {};
    for (int k0 = 0; k0 < 1024; k0 += 16) {
        float4 xa = xg[k0 >> 2];
        float4 ba = ag[k0 >> 2];
        __syncthreads();
        Ax[lc+0][lr]=xa.x; Ax[lc+1][lr]=xa.y; Ax[lc+2][lr]=xa.z; Ax[lc+3][lr]=xa.w;
        Bw[lc+0][lr]=ba.x; Bw[lc+1][lr]=ba.y; Bw[lc+2][lr]=ba.z; Bw[lc+3][lr]=ba.w;
        __syncthreads();
#pragma unroll
        for (int kk = 0; kk < 16; ++kk) {
            float4 a4 = *(const float4*)&Ax[kk][ty * 4];
            float4 b4 = *(const float4*)&Bw[kk][tx * 4];
            float a[4] = {a4.x, a4.y, a4.z, a4.w};
            float b[4] = {b4.x, b4.y, b4.z, b4.w};
#pragma unroll
            for (int i = 0; i < 4; ++i)
#pragma unroll
                for (int j = 0; j < 4; ++j) acc[i][j] += a[i] * b[j];
        }
    }
#pragma unroll
    for (int i = 0; i < 4; ++i)
#pragma unroll
        for (int j = 0; j < 4; ++j)
            atomicAdd(&g_h[(size_t)(m0 + ty * 4 + i) * ERDIM + tx * 4 + j], acc[i][j]);
}

// ================= main HMMA kernel =================
// CTA tile 128x256, BK=64 bf16, 8 warps with 64x64 warp tiles.
// 3-term split: xh*Wh + xh*Wl + xl*Wh, fp32 acc. LoRA folded as final chunk.
#define BM 128
#define BN 256
#define BK 64
#define NT (DDIM / BK)          // 64
#define A_HI 0
#define A_LO 16384
#define B_HI 32768
#define B_LO 65536
#define BUFSZ 98304
#define SMEM_BYTES (2 * BUFSZ)  // 196608

__device__ __forceinline__ void stage_chunk(uint32_t sdst, int tid,
                                            int m0, int n0, int t) {
#pragma unroll
    for (int i = 0; i < 8; ++i) {
        int idx = i * 256 + tid;
        int tile = idx >> 10, rem = idx & 1023;
        int row = rem >> 3, c = rem & 7;
        const __nv_bfloat16* src = (tile ? g_xlo : g_xhi)
            + (size_t)(m0 + row) * DDIM + t * BK + c * 8;
        cp16(sdst + tile * 16384 + row * 128 + ((c ^ (row & 7)) << 4), src);
    }
#pragma unroll
    for (int i = 0; i < 16; ++i) {
        int idx = i * 256 + tid;
        int tile = idx >> 11, rem = idx & 2047;
        int row = rem >> 3, c = rem & 7;
        const __nv_bfloat16* src = (tile ? g_wlo : g_whi)
            + (size_t)(n0 + row) * DDIM + t * BK + c * 8;
        cp16(sdst + B_HI + tile * 32768 + row * 128 + ((c ^ (row & 7)) << 4), src);
    }
}

__device__ __forceinline__ void compute_chunk(uint32_t buf, float acc[4][8][4],
                                              const int arow[4], const int brow[4],
                                              int khalf) {
#pragma unroll
    for (int ks = 0; ks < 4; ++ks) {
        uint32_t ah[4][4], al[4][4];
#pragma unroll
        for (int mf = 0; mf < 4; ++mf) {
            uint32_t off = arow[mf] * 128 + (((2 * ks + khalf) ^ (arow[mf] & 7)) << 4);
            ldsm4(buf + A_HI + off, ah[mf]);
            ldsm4(buf + A_LO + off, al[mf]);
        }
#pragma unroll
        for (int nf2 = 0; nf2 < 4; ++nf2) {
            uint32_t off = brow[nf2] * 128 + (((2 * ks + khalf) ^ (brow[nf2] & 7)) << 4);
            uint32_t bh[4], bl[4];
            ldsm4(buf + B_HI + off, bh);
            ldsm4(buf + B_LO + off, bl);
#pragma unroll
            for (int mf = 0; mf < 4; ++mf) {
                float* d0 = acc[mf][2 * nf2];
                float* d1 = acc[mf][2 * nf2 + 1];
                mma_bf16(d0, ah[mf], bh[0], bh[2]);
                mma_bf16(d1, ah[mf], bh[1], bh[3]);
                mma_bf16(d0, ah[mf], bl[0], bl[2]);
                mma_bf16(d1, ah[mf], bl[1], bl[3]);
                mma_bf16(d0, al[mf], bh[0], bh[2]);
                mma_bf16(d1, al[mf], bh[1], bh[3]);
            }
        }
    }
}

__global__ void __launch_bounds__(256, 1) main_hmma_kernel(
        const float* __restrict__ bias, const float* __restrict__ lB,
        float* __restrict__ out) {
    extern __shared__ __align__(1024) char sm[];
    const int tid = threadIdx.x;
    const int lane = tid & 31, wid = tid >> 5;
    const int wm = wid & 1, wn = wid >> 1;
    const uint32_t sbase = cvta_smem(sm);
    const int n0 = blockIdx.x * BN;
    const int m0 = blockIdx.y * BM;
    const int bidx = m0 >> 11;

    // ldmatrix per-thread geometry
    const int row16 = ((lane >> 3) & 1) * 8 + (lane & 7);
    const int khalf = lane >> 4;
    int arow[4], brow[4];
#pragma unroll
    for (int f = 0; f < 4; ++f) {
        arow[f] = wm * 64 + f * 16 + row16;
        brow[f] = wn * 64 + f * 16 + row16;
    }

    float acc[4][8][4];
#pragma unroll
    for (int i = 0; i < 4; ++i)
#pragma unroll
        for (int j = 0; j < 8; ++j)
#pragma unroll
            for (int k = 0; k < 4; ++k) acc[i][j][k] = 0.0f;

    stage_chunk(sbase, tid, m0, n0, 0);
    cp_commit();

    for (int t = 0; t < NT; ++t) {
        cp_wait0();
        __syncthreads();
        if (t + 1 < NT) {
            stage_chunk(sbase + ((t + 1) & 1) * BUFSZ, tid, m0, n0, t + 1);
            cp_commit();
        }
        compute_chunk(sbase + (t & 1) * BUFSZ, acc, arow, brow, khalf);
    }

    // ---------------- LoRA chunk: A = w*h (split), B = B2 (split) -------
    __syncthreads();
#pragma unroll
    for (int i = 0; i < 8; ++i) {
        int idx = i * 256 + tid;          // 0..2047
        int row = idx >> 4;               // 0..127
        int q = idx & 15;
        int er0 = q * 4;
        float wsc = g_w[bidx * EDIM + (er0 >> 3)];
        float4 hv = *(const float4*)(g_h + (size_t)(m0 + row) * ERDIM + er0);
        hv.x *= wsc; hv.y *= wsc; hv.z *= wsc; hv.w *= wsc;
        uint2 hi, lo;
        split4(hv, hi, lo);
        int so = (row << 7) + (((q >> 1) ^ (row & 7)) << 4) + ((q & 1) << 3);
        *(uint2*)(sm + A_HI + so) = hi;
        *(uint2*)(sm + A_LO + so) = lo;
    }
#pragma unroll
    for (int i = 0; i < 16; ++i) {
        int idx = i * 256 + tid;          // 0..4095
        int row = idx >> 4;               // 0..255
        int q = idx & 15;
        int er0 = q * 4;
        int e = er0 >> 3, r0 = er0 & 7;
        float4 bv = *(const float4*)(lB + (size_t)e * ODIM * RDIM
                                        + (size_t)(n0 + row) * RDIM + r0);
        uint2 hi, lo;
        split4(bv, hi, lo);
        int so = (row << 7) + (((q >> 1) ^ (row & 7)) << 4) + ((q & 1) << 3);
        *(uint2*)(sm + B_HI + so) = hi;
        *(uint2*)(sm + B_LO + so) = lo;
    }
    __syncthreads();
    compute_chunk(sbase, acc, arow, brow, khalf);

    // ---------------- writeback with bias ----------------
    const int r = lane >> 2;
    const int c2 = (lane & 3) * 2;
#pragma unroll
    for (int mf = 0; mf < 4; ++mf) {
        int row0 = m0 + wm * 64 + mf * 16 + r;
#pragma unroll
        for (int nf = 0; nf < 8; ++nf) {
            int col = n0 + wn * 64 + nf * 8 + c2;
            float b0 = __ldg(&bias[col]);
            float b1 = __ldg(&bias[col + 1]);
            float* a4 = acc[mf][nf];
            *(float2*)(out + (size_t)row0 * ODIM + col) =
                make_float2(a4[0] + b0, a4[1] + b1);
            *(float2*)(out + (size_t)(row0 + 8) * ODIM + col) =
                make_float2(a4[2] + b0, a4[3] + b1);
        }
    }
}

// ================= launcher =================
extern "C" void kernel_launch(void* const* d_in, const int* in_sizes, int n_in,
                              void* d_out, int out_size) {
    const float* x   = (const float*)d_in[0];   // [B,S,D]
    const float* Wb  = (const float*)d_in[1];   // [O,D]
    const float* bb  = (const float*)d_in[2];   // [O]
    const float* lA  = (const float*)d_in[3];   // [E,R,D]
    const float* lBm = (const float*)d_in[4];   // [E,O,R]
    const float* rW  = (const float*)d_in[5];   // [E,D]
    const float* rb  = (const float*)d_in[6];   // [E]
    float* out = (float*)d_out;                 // [B,S,O]

    cudaFuncSetAttribute(main_hmma_kernel,
                         cudaFuncAttributeMaxDynamicSharedMemorySize, SMEM_BYTES);

    zero_kernel<<<512, 1024>>>();
    convx_kernel<<<dim3(16, 16, 4), 256>>>(x);
    convw_kernel<<<16384, 256>>>(Wb);
    router_kernel<<<1, 1024>>>(rW, rb);
    h_kernel<<<dim3(128, 4), 256>>>(x, lA);
    main_hmma_kernel<<<dim3(ODIM / BN, MDIM / BM), 256, SMEM_BYTES>>>(bb, lBm, out);
}